// round 3
// baseline (speedup 1.0000x reference)
#include <cuda_runtime.h>

// Problem constants (fixed by the dataset; arrays sized to them)
#define MAXN 100000
#define MAXE 1200000
#define DIM  64
#define MAXG 128

// ---------------- scratch (static device globals; no allocation) -------------
__device__ int   g_indeg[MAXN];
__device__ int   g_fill[MAXN];
__device__ int   g_rowptr[MAXN + 1];
__device__ float g_dinv[MAXN];
__device__ int   g_col[MAXE];
__device__ float g_nrm[MAXE];
__device__ float g_tmp[(size_t)MAXN * DIM];
__device__ float g_h[(size_t)MAXN * DIM];
__device__ float g_pooled[MAXG * DIM];
__device__ int   g_counts[MAXG];
__device__ int   g_idx64;   // 1 if indices are int64, 0 if int32

// Flag-dispatched index load: element i of an index array that is either
// int32[] or int64[] (little-endian; values < 2^31 so low word suffices).
__device__ __forceinline__ int load_idx(const void* p, long long i) {
    if (g_idx64) return (int)((const long long*)p)[i];
    return ((const int*)p)[i];
}

// ---------------- dtype detection (1 thread, reads 64 int32 words) -----------
__global__ void detect_kernel(const int* __restrict__ ei32) {
    // If edge_index is int64, every odd int32 word (high half) of the first 32
    // values is 0. If int32, odd words are random node ids (~never all zero).
    int all_zero = 1;
    for (int k = 0; k < 32; k++)
        if (ei32[2 * k + 1] != 0) all_zero = 0;
    g_idx64 = all_zero;
}

// ---------------- zero scratch that must be clean each launch ----------------
__global__ void zero_kernel(int n, int g) {
    int stride = gridDim.x * blockDim.x;
    for (int i = blockIdx.x * blockDim.x + threadIdx.x; i < n; i += stride) {
        g_indeg[i] = 0;
        g_fill[i] = 0;
    }
    for (int i = blockIdx.x * blockDim.x + threadIdx.x; i < g * DIM; i += stride)
        g_pooled[i] = 0.0f;
    for (int i = blockIdx.x * blockDim.x + threadIdx.x; i < g; i += stride)
        g_counts[i] = 0;
}

// ---------------- degree histogram (at destination) --------------------------
// edge_index layout [2, E]: element (e + i) is dst[i] in either dtype.
__global__ void degree_kernel(const void* __restrict__ ei, int e) {
    int stride = gridDim.x * blockDim.x;
    for (int i = blockIdx.x * blockDim.x + threadIdx.x; i < e; i += stride)
        atomicAdd(&g_indeg[load_idx(ei, (long long)e + i)], 1);
}

__global__ void dinv_kernel(int n) {
    int i = blockIdx.x * blockDim.x + threadIdx.x;
    if (i < n)
        g_dinv[i] = rsqrtf((float)g_indeg[i] + 1.0f);
}

// ---------------- single-block exclusive scan of indeg -> rowptr -------------
__global__ void scan_kernel(int n) {
    __shared__ int s[1024];
    int t = threadIdx.x;
    int seg = (n + 1023) / 1024;
    int base = t * seg;
    int sum = 0;
    for (int j = 0; j < seg; j++) {
        int i = base + j;
        if (i < n) sum += g_indeg[i];
    }
    s[t] = sum;
    __syncthreads();
    for (int off = 1; off < 1024; off <<= 1) {
        int v = (t >= off) ? s[t - off] : 0;
        __syncthreads();
        s[t] += v;
        __syncthreads();
    }
    int run = (t == 0) ? 0 : s[t - 1];
    for (int j = 0; j < seg; j++) {
        int i = base + j;
        if (i < n) {
            g_rowptr[i] = run;
            run += g_indeg[i];
        }
    }
    if (t == 1023)
        g_rowptr[n] = run;   // total = E
}

// ---------------- CSR fill: col (src) + per-edge norm ------------------------
__global__ void fill_kernel(const void* __restrict__ ei, int e) {
    int stride = gridDim.x * blockDim.x;
    for (int i = blockIdx.x * blockDim.x + threadIdx.x; i < e; i += stride) {
        int s = load_idx(ei, i);                     // src row
        int d = load_idx(ei, (long long)e + i);      // dst row
        int pos = g_rowptr[d] + atomicAdd(&g_fill[d], 1);
        g_col[pos] = s;
        g_nrm[pos] = g_dinv[s] * g_dinv[d];
    }
}

// ---------------- dense GEMM: g_tmp[n,64] = in[n,64] @ W[64,64] --------------
// in == nullptr means "read from g_h". Output always goes to g_tmp.
// Block tile: 64 nodes x 64 cols, 256 threads, 4x4 register micro-tiles.
__global__ __launch_bounds__(256) void gemm64_kernel(
    const float* __restrict__ in, const float* __restrict__ W, int n) {
    __shared__ float sX[64][68];
    __shared__ float sW[64][68];
    const float* src = (in == nullptr) ? g_h : in;
    int t = threadIdx.x;
    int block0 = blockIdx.x * 64;

    // stage W (row r = k, col c) and X tile with float4 loads
    for (int i = t; i < 64 * 16; i += 256) {
        int r = i >> 4;
        int c4 = (i & 15) << 2;
        float4 w4 = *(const float4*)&W[r * 64 + c4];
        *(float4*)&sW[r][c4] = w4;
        int node = block0 + r;
        float4 x4 = make_float4(0.f, 0.f, 0.f, 0.f);
        if (node < n)
            x4 = *(const float4*)&src[(size_t)node * 64 + c4];
        *(float4*)&sX[r][c4] = x4;
    }
    __syncthreads();

    int tc = (t & 15) << 2;   // output col base
    int tr = (t >> 4) << 2;   // node base within tile
    float acc[4][4] = {};
#pragma unroll
    for (int k = 0; k < 64; k++) {
        float4 b4 = *(const float4*)&sW[k][tc];
        float a0 = sX[tr + 0][k];
        float a1 = sX[tr + 1][k];
        float a2 = sX[tr + 2][k];
        float a3 = sX[tr + 3][k];
        acc[0][0] += a0 * b4.x; acc[0][1] += a0 * b4.y; acc[0][2] += a0 * b4.z; acc[0][3] += a0 * b4.w;
        acc[1][0] += a1 * b4.x; acc[1][1] += a1 * b4.y; acc[1][2] += a1 * b4.z; acc[1][3] += a1 * b4.w;
        acc[2][0] += a2 * b4.x; acc[2][1] += a2 * b4.y; acc[2][2] += a2 * b4.z; acc[2][3] += a2 * b4.w;
        acc[3][0] += a3 * b4.x; acc[3][1] += a3 * b4.y; acc[3][2] += a3 * b4.z; acc[3][3] += a3 * b4.w;
    }
#pragma unroll
    for (int i = 0; i < 4; i++) {
        int node = block0 + tr + i;
        if (node < n)
            *(float4*)&g_tmp[(size_t)node * 64 + tc] =
                make_float4(acc[i][0], acc[i][1], acc[i][2], acc[i][3]);
    }
}

// ---------------- aggregation: warp per node, gather over CSR row ------------
// g_h[i] = relu( sum_e g_tmp[col[e]]*nrm[e] + g_tmp[i]*dinv[i]^2 + b )
__global__ __launch_bounds__(256) void aggregate_kernel(
    const float* __restrict__ b, int n) {
    int warp = (blockIdx.x * blockDim.x + threadIdx.x) >> 5;
    int lane = threadIdx.x & 31;
    if (warp >= n) return;
    int i = warp;
    int s = g_rowptr[i];
    int e = g_rowptr[i + 1];
    float di = g_dinv[i];
    float2 hv = *(const float2*)&g_tmp[(size_t)i * 64 + lane * 2];
    float2 acc;
    acc.x = hv.x * di * di;
    acc.y = hv.y * di * di;

    // software-pipelined gather (hide index-load -> data-load dependency)
    int p = s;
    int src = 0;
    float w = 0.f;
    if (p < e) { src = g_col[p]; w = g_nrm[p]; }
    while (p < e) {
        int p2 = p + 1;
        int src2 = 0;
        float w2 = 0.f;
        if (p2 < e) { src2 = g_col[p2]; w2 = g_nrm[p2]; }
        float2 v = *(const float2*)&g_tmp[(size_t)src * 64 + lane * 2];
        acc.x += v.x * w;
        acc.y += v.y * w;
        src = src2; w = w2; p = p2;
    }
    float2 bb = *(const float2*)&b[lane * 2];
    acc.x = fmaxf(acc.x + bb.x, 0.f);
    acc.y = fmaxf(acc.y + bb.y, 0.f);
    *(float2*)&g_h[(size_t)i * 64 + lane * 2] = acc;
}

// ---------------- pooling: exploit sorted batch, flush per graph-run ---------
__global__ void pool_kernel(const void* __restrict__ batch, int n) {
    int warp = (blockIdx.x * blockDim.x + threadIdx.x) >> 5;
    int lane = threadIdx.x & 31;
    int base = warp * 64;
    if (base >= n) return;
    int end = min(base + 64, n);
    int cg = load_idx(batch, base);
    int run = 0;
    float2 acc = make_float2(0.f, 0.f);
    for (int i = base; i < end; i++) {
        int g = load_idx(batch, i);
        if (g != cg) {
            atomicAdd(&g_pooled[cg * 64 + lane * 2 + 0], acc.x);
            atomicAdd(&g_pooled[cg * 64 + lane * 2 + 1], acc.y);
            if (lane == 0) atomicAdd(&g_counts[cg], run);
            acc = make_float2(0.f, 0.f);
            run = 0;
            cg = g;
        }
        float2 v = *(const float2*)&g_h[(size_t)i * 64 + lane * 2];
        acc.x += v.x;
        acc.y += v.y;
        run++;
    }
    atomicAdd(&g_pooled[cg * 64 + lane * 2 + 0], acc.x);
    atomicAdd(&g_pooled[cg * 64 + lane * 2 + 1], acc.y);
    if (lane == 0) atomicAdd(&g_counts[cg], run);
}

// ---------------- final: mean + linear head ----------------------------------
__global__ void final_kernel(const float* __restrict__ lin_w,
                             const float* __restrict__ lin_b,
                             float* __restrict__ out, int g) {
    int i = blockIdx.x * blockDim.x + threadIdx.x;
    if (i >= g) return;
    float cnt = fmaxf((float)g_counts[i], 1.0f);
    float inv = 1.0f / cnt;
    float a0 = lin_b[0];
    float a1 = lin_b[1];
#pragma unroll
    for (int d = 0; d < 64; d++) {
        float p = g_pooled[i * 64 + d] * inv;
        a0 += p * lin_w[d * 2 + 0];
        a1 += p * lin_w[d * 2 + 1];
    }
    out[i * 2 + 0] = a0;
    out[i * 2 + 1] = a1;
}

// ---------------- launch ------------------------------------------------------
extern "C" void kernel_launch(void* const* d_in, const int* in_sizes, int n_in,
                              void* d_out, int out_size) {
    const float* x     = (const float*)d_in[0];
    const void*  ei    = d_in[1];
    const void*  batch = d_in[2];
    const float* W0    = (const float*)d_in[3];
    const float* b0    = (const float*)d_in[4];
    const float* W1    = (const float*)d_in[5];
    const float* b1    = (const float*)d_in[6];
    const float* W2    = (const float*)d_in[7];
    const float* b2    = (const float*)d_in[8];
    const float* lin_w = (const float*)d_in[9];
    const float* lin_b = (const float*)d_in[10];

    int n = in_sizes[0] / DIM;       // 100000
    int e = in_sizes[1] / 2;         // 1200000
    int nc = in_sizes[10];           // 2
    int g = out_size / nc;           // 128

    detect_kernel<<<1, 1>>>((const int*)ei);
    zero_kernel<<<256, 256>>>(n, g);
    degree_kernel<<<(e + 255) / 256, 256>>>(ei, e);
    dinv_kernel<<<(n + 255) / 256, 256>>>(n);
    scan_kernel<<<1, 1024>>>(n);
    fill_kernel<<<(e + 255) / 256, 256>>>(ei, e);

    int gemm_blocks = (n + 63) / 64;
    int agg_blocks = (n * 32 + 255) / 256;

    gemm64_kernel<<<gemm_blocks, 256>>>(x, W0, n);
    aggregate_kernel<<<agg_blocks, 256>>>(b0, n);
    gemm64_kernel<<<gemm_blocks, 256>>>(nullptr, W1, n);
    aggregate_kernel<<<agg_blocks, 256>>>(b1, n);
    gemm64_kernel<<<gemm_blocks, 256>>>(nullptr, W2, n);
    aggregate_kernel<<<agg_blocks, 256>>>(b2, n);

    int pool_blocks = ((n + 63) / 64 * 32 + 255) / 256;
    pool_kernel<<<pool_blocks, 256>>>(batch, n);
    final_kernel<<<1, 128>>>(lin_w, lin_b, (float*)d_out, g);
}

// round 4
// speedup vs baseline: 1.3380x; 1.3380x over previous
#include <cuda_runtime.h>

// Problem constants (fixed by the dataset; arrays sized to them)
#define MAXN 100000
#define MAXE 1200000
#define DIM  64
#define MAXG 128
#define SCAN_B 1024   // elements per scan block

// ---------------- scratch (static device globals; no allocation) -------------
__device__ int   g_indeg[MAXN];
__device__ int   g_fill[MAXN];        // doubles as CSR cursor (init = rowptr)
__device__ int   g_rowptr[MAXN + 1];
__device__ float g_dinv[MAXN];
__device__ int   g_col[MAXE];
__device__ float g_nrm[MAXE];
__device__ float g_tmp[(size_t)MAXN * DIM];
__device__ float g_h[(size_t)MAXN * DIM];
__device__ float g_pooled[MAXG * DIM];
__device__ int   g_counts[MAXG];
__device__ int   g_bsum[1024];        // per-block degree sums
__device__ int   g_boff[1024];        // exclusive block offsets
__device__ int   g_idx64;             // 1 if indices are int64, 0 if int32

// Flag-dispatched index load (int32[] or int64[]; values < 2^31).
__device__ __forceinline__ int load_idx(const void* p, long long i) {
    if (g_idx64) return (int)((const long long*)p)[i];
    return ((const int*)p)[i];
}

// ---------------- packed f32x2 helpers (Blackwell) ---------------------------
__device__ __forceinline__ unsigned long long pack2(float x, float y) {
    unsigned long long r;
    asm("mov.b64 %0,{%1,%2};" : "=l"(r) : "f"(x), "f"(y));
    return r;
}
__device__ __forceinline__ void fma2(unsigned long long& d,
                                     unsigned long long a,
                                     unsigned long long b) {
    asm("fma.rn.f32x2 %0,%1,%2,%0;" : "+l"(d) : "l"(a), "l"(b));
}

// ---------------- detect dtype + zero small scratch --------------------------
__global__ void detect_zero_kernel(const int* __restrict__ ei32, int g) {
    int t = threadIdx.x;
    if (t == 0) {
        // int64 edge_index => every odd int32 word (high half) of the first
        // 32 values is 0. int32 => odd words are random node ids.
        int all_zero = 1;
        for (int k = 0; k < 32; k++)
            if (ei32[2 * k + 1] != 0) all_zero = 0;
        g_idx64 = all_zero;
    }
    for (int i = t; i < g * DIM; i += blockDim.x) g_pooled[i] = 0.0f;
    for (int i = t; i < g; i += blockDim.x) g_counts[i] = 0;
}

__global__ void zero_indeg_kernel(int n) {
    int stride = gridDim.x * blockDim.x;
    for (int i = blockIdx.x * blockDim.x + threadIdx.x; i < n; i += stride)
        g_indeg[i] = 0;
}

// ---------------- degree histogram (at destination) --------------------------
__global__ void degree_kernel(const void* __restrict__ ei, int e) {
    int stride = gridDim.x * blockDim.x;
    for (int i = blockIdx.x * blockDim.x + threadIdx.x; i < e; i += stride)
        atomicAdd(&g_indeg[load_idx(ei, (long long)e + i)], 1);
}

// ---------------- 3-phase scan: indeg -> rowptr (+fill cursor, +dinv) --------
__global__ void scan1_kernel(int n) {            // per-block sums
    __shared__ int wsum[32];
    int b = blockIdx.x, t = threadIdx.x;
    int i = b * SCAN_B + t;
    int lane = t & 31, wi = t >> 5;
    int v = (i < n) ? g_indeg[i] : 0;
#pragma unroll
    for (int off = 16; off > 0; off >>= 1)
        v += __shfl_down_sync(0xffffffffu, v, off);
    if (lane == 0) wsum[wi] = v;
    __syncthreads();
    if (wi == 0) {
        int s = wsum[lane];
#pragma unroll
        for (int off = 16; off > 0; off >>= 1)
            s += __shfl_down_sync(0xffffffffu, s, off);
        if (lane == 0) g_bsum[b] = s;
    }
}

__global__ void scan2_kernel(int nb) {           // scan block sums (1 block)
    __shared__ int s[1024];
    int t = threadIdx.x;
    int v = (t < nb) ? g_bsum[t] : 0;
    s[t] = v;
    __syncthreads();
    for (int off = 1; off < 1024; off <<= 1) {
        int y = (t >= off) ? s[t - off] : 0;
        __syncthreads();
        s[t] += y;
        __syncthreads();
    }
    if (t < nb) g_boff[t] = s[t] - v;            // exclusive
}

__global__ void scan3_kernel(int n) {            // rowptr + fill + dinv
    __shared__ int wtot[32];
    int b = blockIdx.x, t = threadIdx.x;
    int i = b * SCAN_B + t;
    int lane = t & 31, wi = t >> 5;
    int v = (i < n) ? g_indeg[i] : 0;
    int x = v;
#pragma unroll
    for (int off = 1; off < 32; off <<= 1) {     // inclusive warp scan
        int y = __shfl_up_sync(0xffffffffu, x, off);
        if (lane >= off) x += y;
    }
    if (lane == 31) wtot[wi] = x;
    __syncthreads();
    if (wi == 0) {
        int y = wtot[lane];
        int z = y;
#pragma unroll
        for (int off = 1; off < 32; off <<= 1) {
            int u = __shfl_up_sync(0xffffffffu, z, off);
            if (lane >= off) z += u;
        }
        wtot[lane] = z - y;                      // exclusive warp offsets
    }
    __syncthreads();
    if (i < n) {
        int excl = x - v + wtot[wi] + g_boff[b];
        g_rowptr[i] = excl;
        g_fill[i]   = excl;                      // cursor starts at rowptr
        g_dinv[i]   = rsqrtf((float)v + 1.0f);
        if (i == n - 1) g_rowptr[n] = excl + v;
    }
}

// ---------------- CSR fill: col (src) + per-edge norm ------------------------
__global__ void fill_kernel(const void* __restrict__ ei, int e) {
    int stride = gridDim.x * blockDim.x;
    for (int i = blockIdx.x * blockDim.x + threadIdx.x; i < e; i += stride) {
        int s = load_idx(ei, i);                 // src row
        int d = load_idx(ei, (long long)e + i);  // dst row
        int pos = atomicAdd(&g_fill[d], 1);      // cursor = absolute position
        g_col[pos] = s;
        g_nrm[pos] = g_dinv[s] * g_dinv[d];
    }
}

// ---------------- dense GEMM: g_tmp[n,64] = in[n,64] @ W[64,64] --------------
// in == nullptr means "read from g_h". 64x64 tile, 256 thr, FFMA2 micro-tiles.
__global__ __launch_bounds__(256) void gemm64_kernel(
    const float* __restrict__ in, const float* __restrict__ W, int n) {
    __shared__ float sX[64][68];
    __shared__ float sW[64][68];
    const float* src = (in == nullptr) ? g_h : in;
    int t = threadIdx.x;
    int block0 = blockIdx.x * 64;

    for (int i = t; i < 64 * 16; i += 256) {
        int r = i >> 4;
        int c4 = (i & 15) << 2;
        *(float4*)&sW[r][c4] = *(const float4*)&W[r * 64 + c4];
        int node = block0 + r;
        float4 x4 = make_float4(0.f, 0.f, 0.f, 0.f);
        if (node < n)
            x4 = *(const float4*)&src[(size_t)node * 64 + c4];
        *(float4*)&sX[r][c4] = x4;
    }
    __syncthreads();

    int tc = (t & 15) << 2;   // output col base (16B aligned in sW row)
    int tr = (t >> 4) << 2;   // node base within tile
    unsigned long long acc[4][2] = {};
#pragma unroll
    for (int k = 0; k < 64; k++) {
        const unsigned long long* bp = (const unsigned long long*)&sW[k][tc];
        unsigned long long b01 = bp[0];
        unsigned long long b23 = bp[1];
#pragma unroll
        for (int i = 0; i < 4; i++) {
            float a = sX[tr + i][k];
            unsigned long long aa = pack2(a, a);
            fma2(acc[i][0], aa, b01);
            fma2(acc[i][1], aa, b23);
        }
    }
    union U { unsigned long long u; float2 f; };
#pragma unroll
    for (int i = 0; i < 4; i++) {
        int node = block0 + tr + i;
        if (node < n) {
            U u0, u1;
            u0.u = acc[i][0];
            u1.u = acc[i][1];
            *(float4*)&g_tmp[(size_t)node * 64 + tc] =
                make_float4(u0.f.x, u0.f.y, u1.f.x, u1.f.y);
        }
    }
}

// ---------------- aggregation: warp/node, half-warp/edge, float4 lanes -------
// g_h[i] = relu( sum_e g_tmp[col[e]]*nrm[e] + g_tmp[i]*dinv[i]^2 + b )
__global__ __launch_bounds__(256) void aggregate_kernel(
    const float* __restrict__ b, int n) {
    int warp = (blockIdx.x * blockDim.x + threadIdx.x) >> 5;
    if (warp >= n) return;
    int lane = threadIdx.x & 31;
    int half = lane >> 4;     // which edge of the pair
    int q = lane & 15;        // feature group (float4)
    int s = g_rowptr[warp];
    int e = g_rowptr[warp + 1];
    float di = g_dinv[warp];

    float4 acc = make_float4(0.f, 0.f, 0.f, 0.f);
    if (half == 0) {          // self-loop term once
        float4 hv = *(const float4*)&g_tmp[(size_t)warp * 64 + q * 4];
        float d2 = di * di;
        acc.x = hv.x * d2; acc.y = hv.y * d2;
        acc.z = hv.z * d2; acc.w = hv.w * d2;
    }

    // two edges per warp-iteration, software-pipelined index fetch
    int p = s + half;
    int src = 0;
    float w = 0.f;
    if (p < e) { src = g_col[p]; w = g_nrm[p]; }
    while (p < e) {
        int pn = p + 2;
        int src2 = 0;
        float w2 = 0.f;
        if (pn < e) { src2 = g_col[pn]; w2 = g_nrm[pn]; }
        float4 v = *(const float4*)&g_tmp[(size_t)src * 64 + q * 4];
        acc.x += v.x * w; acc.y += v.y * w;
        acc.z += v.z * w; acc.w += v.w * w;
        p = pn; src = src2; w = w2;
    }

    // combine the two half-warp accumulators
    acc.x += __shfl_down_sync(0xffffffffu, acc.x, 16);
    acc.y += __shfl_down_sync(0xffffffffu, acc.y, 16);
    acc.z += __shfl_down_sync(0xffffffffu, acc.z, 16);
    acc.w += __shfl_down_sync(0xffffffffu, acc.w, 16);

    if (half == 0) {
        float4 bb = *(const float4*)&b[q * 4];
        acc.x = fmaxf(acc.x + bb.x, 0.f);
        acc.y = fmaxf(acc.y + bb.y, 0.f);
        acc.z = fmaxf(acc.z + bb.z, 0.f);
        acc.w = fmaxf(acc.w + bb.w, 0.f);
        *(float4*)&g_h[(size_t)warp * 64 + q * 4] = acc;
    }
}

// ---------------- pooling: exploit sorted batch, flush per graph-run ---------
__global__ void pool_kernel(const void* __restrict__ batch, int n) {
    int warp = (blockIdx.x * blockDim.x + threadIdx.x) >> 5;
    int lane = threadIdx.x & 31;
    int base = warp * 64;
    if (base >= n) return;
    int end = min(base + 64, n);
    int cg = load_idx(batch, base);
    int run = 0;
    float2 acc = make_float2(0.f, 0.f);
    for (int i = base; i < end; i++) {
        int g = load_idx(batch, i);
        if (g != cg) {
            atomicAdd(&g_pooled[cg * 64 + lane * 2 + 0], acc.x);
            atomicAdd(&g_pooled[cg * 64 + lane * 2 + 1], acc.y);
            if (lane == 0) atomicAdd(&g_counts[cg], run);
            acc = make_float2(0.f, 0.f);
            run = 0;
            cg = g;
        }
        float2 v = *(const float2*)&g_h[(size_t)i * 64 + lane * 2];
        acc.x += v.x;
        acc.y += v.y;
        run++;
    }
    atomicAdd(&g_pooled[cg * 64 + lane * 2 + 0], acc.x);
    atomicAdd(&g_pooled[cg * 64 + lane * 2 + 1], acc.y);
    if (lane == 0) atomicAdd(&g_counts[cg], run);
}

// ---------------- final: mean + linear head ----------------------------------
__global__ void final_kernel(const float* __restrict__ lin_w,
                             const float* __restrict__ lin_b,
                             float* __restrict__ out, int g) {
    int i = blockIdx.x * blockDim.x + threadIdx.x;
    if (i >= g) return;
    float cnt = fmaxf((float)g_counts[i], 1.0f);
    float inv = 1.0f / cnt;
    float a0 = lin_b[0];
    float a1 = lin_b[1];
#pragma unroll
    for (int d = 0; d < 64; d++) {
        float p = g_pooled[i * 64 + d] * inv;
        a0 += p * lin_w[d * 2 + 0];
        a1 += p * lin_w[d * 2 + 1];
    }
    out[i * 2 + 0] = a0;
    out[i * 2 + 1] = a1;
}

// ---------------- launch ------------------------------------------------------
extern "C" void kernel_launch(void* const* d_in, const int* in_sizes, int n_in,
                              void* d_out, int out_size) {
    const float* x     = (const float*)d_in[0];
    const void*  ei    = d_in[1];
    const void*  batch = d_in[2];
    const float* W0    = (const float*)d_in[3];
    const float* b0    = (const float*)d_in[4];
    const float* W1    = (const float*)d_in[5];
    const float* b1    = (const float*)d_in[6];
    const float* W2    = (const float*)d_in[7];
    const float* b2    = (const float*)d_in[8];
    const float* lin_w = (const float*)d_in[9];
    const float* lin_b = (const float*)d_in[10];

    int n = in_sizes[0] / DIM;       // 100000
    int e = in_sizes[1] / 2;         // 1200000
    int nc = in_sizes[10];           // 2
    int g = out_size / nc;           // 128

    int nb = (n + SCAN_B - 1) / SCAN_B;   // 98 scan blocks

    detect_zero_kernel<<<1, 256>>>((const int*)ei, g);
    zero_indeg_kernel<<<200, 512>>>(n);
    degree_kernel<<<(e + 511) / 512, 512>>>(ei, e);
    scan1_kernel<<<nb, SCAN_B>>>(n);
    scan2_kernel<<<1, 1024>>>(nb);
    scan3_kernel<<<nb, SCAN_B>>>(n);
    fill_kernel<<<(e + 511) / 512, 512>>>(ei, e);

    int gemm_blocks = (n + 63) / 64;
    long long agg_threads = (long long)n * 32;
    int agg_blocks = (int)((agg_threads + 255) / 256);

    gemm64_kernel<<<gemm_blocks, 256>>>(x, W0, n);
    aggregate_kernel<<<agg_blocks, 256>>>(b0, n);
    gemm64_kernel<<<gemm_blocks, 256>>>(nullptr, W1, n);
    aggregate_kernel<<<agg_blocks, 256>>>(b1, n);
    gemm64_kernel<<<gemm_blocks, 256>>>(nullptr, W2, n);
    aggregate_kernel<<<agg_blocks, 256>>>(b2, n);

    int pool_blocks = ((n + 63) / 64 * 32 + 255) / 256;
    pool_kernel<<<pool_blocks, 256>>>(batch, n);
    final_kernel<<<1, 128>>>(lin_w, lin_b, (float*)d_out, g);
}